// round 2
// baseline (speedup 1.0000x reference)
#include <cuda_runtime.h>
#include <cooperative_groups.h>
namespace cg = cooperative_groups;

// Problem constants
#define BATCH  8
#define NPTS   32768
#define NSAMP  8192
#define FEATC  256
#define CSIZE  8                 // cluster size (CTAs per batch)
#define TPB    512               // threads per CTA
#define PPC    (NPTS / CSIZE)    // 4096 points per CTA
#define PPT    (PPC / TPB)       // 8 points per thread
#define NWARP  (TPB / 32)        // 16 warps

// Sampled indices, produced by fps_kernel, consumed by gather_kernel.
__device__ int g_idx[BATCH * NSAMP];

// ---------------------------------------------------------------------------
// FPS kernel: one 8-CTA cluster per batch. All point coords + min_dist live
// in registers (8 points/thread). Per iteration:
//   update md, track per-thread argmax -> warp shuffle reduce -> block reduce
//   -> broadcast CTA candidate to all 8 ranks via DSMEM -> cluster.sync
//   -> local 8-way combine gives the global winner (value, index, coords).
// Tie-break everywhere: higher value wins; on equal value, LOWER index wins
// (matches jnp.argmax first-occurrence semantics).
//
// Distance formula replicates XLA/NVPTX fp-contraction EXACTLY:
//   d = fma(dz, dz, fma(dx, dx, dy*dy))
// (DAG combiner on ((dx*dx + dy*dy) + dz*dz) with AllowFPOpFusion=Fast:
//  first fadd(mul,mul) fuses N0 -> fma(dx,dx, dy*dy); second fadd(fma,mul)
//  fuses N1 -> fma(dz,dz, t).) Bit-exact match is required because argmax
//  near-ties are decided at 1-ulp granularity.
// ---------------------------------------------------------------------------
__global__ void __cluster_dims__(CSIZE, 1, 1) __launch_bounds__(TPB, 1)
fps_kernel(const float* __restrict__ xyz)
{
    cg::cluster_group cluster = cg::this_cluster();
    const int rank  = cluster.block_rank();
    const int batch = blockIdx.x / CSIZE;
    const int tid   = threadIdx.x;
    const int lane  = tid & 31;
    const int wid   = tid >> 5;

    const float* __restrict__ xb = xyz + (size_t)batch * NPTS * 3;

    __shared__ float s_wv[NWARP];
    __shared__ int   s_wi[NWARP];
    __shared__ float s_wx[NWARP], s_wy[NWARP], s_wz[NWARP];
    // Double-buffered cluster candidate slots: [buf][src_rank][v,i,x,y,z,...]
    __shared__ alignas(16) float s_slot[2][CSIZE][8];

    // Register-resident point coords and running min distances.
    float px[PPT], py[PPT], pz[PPT], md[PPT];
#pragma unroll
    for (int j = 0; j < PPT; j++) {
        const int p = rank * PPC + j * TPB + tid;
        px[j] = xb[3 * p + 0];
        py[j] = xb[3 * p + 1];
        pz[j] = xb[3 * p + 2];
        md[j] = 1e10f;           // BIG from the reference
    }

    // First sampled point is index 0 (deterministic variant).
    float cx = xb[0], cy = xb[1], cz = xb[2];
    if (rank == 0 && tid == 0) g_idx[batch * NSAMP] = 0;

    for (int k = 1; k < NSAMP; k++) {
        // --- per-thread: update min_dist, track local argmax ---
        float bv = -1.0f;        // distances are >= 0
        int   bi = 0x7fffffff;
        float bx = 0.f, by = 0.f, bz = 0.f;
#pragma unroll
        for (int j = 0; j < PPT; j++) {
            const float dx = __fsub_rn(px[j], cx);
            const float dy = __fsub_rn(py[j], cy);
            const float dz = __fsub_rn(pz[j], cz);
            // XLA-contracted form: fma(dz,dz, fma(dx,dx, dy*dy))
            const float d  = __fmaf_rn(dz, dz,
                              __fmaf_rn(dx, dx, __fmul_rn(dy, dy)));
            const float m  = fminf(md[j], d);
            md[j] = m;
            // strict > : earlier (lower) index wins ties within this thread
            if (m > bv) {
                bv = m; bi = rank * PPC + j * TPB + tid;
                bx = px[j]; by = py[j]; bz = pz[j];
            }
        }

        // --- warp shuffle argmax reduce ---
#pragma unroll
        for (int off = 16; off; off >>= 1) {
            const float ov = __shfl_down_sync(0xffffffffu, bv, off);
            const int   oi = __shfl_down_sync(0xffffffffu, bi, off);
            const float ox = __shfl_down_sync(0xffffffffu, bx, off);
            const float oy = __shfl_down_sync(0xffffffffu, by, off);
            const float oz = __shfl_down_sync(0xffffffffu, bz, off);
            if (ov > bv || (ov == bv && oi < bi)) {
                bv = ov; bi = oi; bx = ox; by = oy; bz = oz;
            }
        }
        if (lane == 0) {
            s_wv[wid] = bv; s_wi[wid] = bi;
            s_wx[wid] = bx; s_wy[wid] = by; s_wz[wid] = bz;
        }
        __syncthreads();

        // --- warp 0: reduce the 16 warp candidates, publish to all ranks ---
        if (wid == 0) {
            bv = (lane < NWARP) ? s_wv[lane] : -2.0f;
            bi = (lane < NWARP) ? s_wi[lane] : 0x7fffffff;
            bx = (lane < NWARP) ? s_wx[lane] : 0.f;
            by = (lane < NWARP) ? s_wy[lane] : 0.f;
            bz = (lane < NWARP) ? s_wz[lane] : 0.f;
#pragma unroll
            for (int off = 16; off; off >>= 1) {
                const float ov = __shfl_down_sync(0xffffffffu, bv, off);
                const int   oi = __shfl_down_sync(0xffffffffu, bi, off);
                const float ox = __shfl_down_sync(0xffffffffu, bx, off);
                const float oy = __shfl_down_sync(0xffffffffu, by, off);
                const float oz = __shfl_down_sync(0xffffffffu, bz, off);
                if (ov > bv || (ov == bv && oi < bi)) {
                    bv = ov; bi = oi; bx = ox; by = oy; bz = oz;
                }
            }
            if (lane == 0) {
                const int buf = k & 1;
                const float4 v4 = make_float4(bv, __int_as_float(bi), bx, by);
#pragma unroll
                for (int r = 0; r < CSIZE; r++) {
                    float* dst = (float*)cluster.map_shared_rank(
                        (void*)&s_slot[buf][rank][0], r);
                    *(float4*)dst = v4;
                    dst[4] = bz;
                }
            }
        }

        // release DSMEM stores + block barrier + acquire remote stores
        cluster.sync();

        // --- every thread combines the 8 CTA candidates locally ---
        const int buf = k & 1;
        float wv = -3.0f; int wi = 0x7fffffff;
        float wx = 0.f, wy = 0.f, wz = 0.f;
#pragma unroll
        for (int r = 0; r < CSIZE; r++) {
            const float sv = s_slot[buf][r][0];
            const int   si = __float_as_int(s_slot[buf][r][1]);
            if (sv > wv || (sv == wv && si < wi)) {
                wv = sv; wi = si;
                wx = s_slot[buf][r][2];
                wy = s_slot[buf][r][3];
                wz = s_slot[buf][r][4];
            }
        }
        cx = wx; cy = wy; cz = wz;
        if (rank == 0 && tid == 0) g_idx[batch * NSAMP + k] = wi;
    }
}

// ---------------------------------------------------------------------------
// Gather kernel: one block per sampled row. Copies 256 feature floats
// (64 threads x float4) and the 3 xyz floats.
// Output layout: [sampled_xyz (B,S,3)] then [sampled_feature (B,S,256)].
// ---------------------------------------------------------------------------
__global__ void __launch_bounds__(64)
gather_kernel(const float* __restrict__ xyz, const float* __restrict__ feat,
              float* __restrict__ out)
{
    const int row = blockIdx.x;          // 0 .. BATCH*NSAMP-1
    const int b = row / NSAMP;
    const int p = g_idx[row];

    float* out_xyz  = out;
    float* out_feat = out + (size_t)BATCH * NSAMP * 3;

    const float4* src = (const float4*)(feat + ((size_t)b * NPTS + p) * FEATC);
    float4*       dst = (float4*)(out_feat + (size_t)row * FEATC);
    dst[threadIdx.x] = src[threadIdx.x];  // 64 * 16B = 1024B per row

    if (threadIdx.x < 3) {
        out_xyz[(size_t)row * 3 + threadIdx.x] =
            xyz[((size_t)b * NPTS + p) * 3 + threadIdx.x];
    }
}

extern "C" void kernel_launch(void* const* d_in, const int* in_sizes, int n_in,
                              void* d_out, int out_size)
{
    const float* xyz  = (const float*)d_in[0];
    const float* feat = (const float*)d_in[1];
    float*       out  = (float*)d_out;

    fps_kernel<<<BATCH * CSIZE, TPB>>>(xyz);
    gather_kernel<<<BATCH * NSAMP, 64>>>(xyz, feat, out);
}

// round 4
// speedup vs baseline: 1.5542x; 1.5542x over previous
#include <cuda_runtime.h>
#include <cooperative_groups.h>
#include <cstdint>
namespace cg = cooperative_groups;

// Problem constants
#define BATCH  8
#define NPTS   32768
#define NSAMP  8192
#define FEATC  256
#define CSIZE  8                 // cluster size (CTAs per batch) -- proven in R2
#define TPB    512
#define PPC    (NPTS / CSIZE)    // 4096 points per CTA
#define PPT    (PPC / TPB)       // 8 points per thread
#define NWARP  (TPB / 32)        // 16

// Sampled indices, produced by fps_kernel, consumed by gather_kernel.
__device__ int g_idx[BATCH * NSAMP];

// ---------------------------------------------------------------------------
// FPS kernel: one 8-CTA cluster per batch (R2-proven skeleton: static
// __cluster_dims__, cluster.sync for the cross-CTA exchange).
//
// Per iteration:
//   compute + per-thread argmax (coords carried via select)
//   -> warp argmax via REDUX (max of value bits, then min index among matches)
//   -> __syncthreads -> warp0 REDUX over the 16 warp winners
//   -> warp0 lanes 0..7 each write the CTA candidate into one rank's
//      double-buffered DSMEM slot (parallel fan-out)
//   -> cluster.sync()  (cluster-scope release/acquire, proven in R2)
//   -> per-warp REDUX combine over the 8 slots -> global winner + coords.
//
// Tie-break everywhere: max value, then MIN global index. Point indices are
// globally unique, so "min index among lanes matching the max" is one-hot and
// equals jnp.argmax first-occurrence semantics at every level. Value bits as
// u32 max is exact for nonnegative floats.
//
// Distance formula replicates XLA/NVPTX fp contraction exactly (verified
// bit-exact in R2):  d = fma(dz, dz, fma(dx, dx, dy*dy))
// ---------------------------------------------------------------------------
__global__ void __cluster_dims__(CSIZE, 1, 1) __launch_bounds__(TPB, 1)
fps_kernel(const float* __restrict__ xyz)
{
    cg::cluster_group cluster = cg::this_cluster();
    const int rank  = cluster.block_rank();
    const int batch = blockIdx.x / CSIZE;
    const int tid   = threadIdx.x;
    const int lane  = tid & 31;
    const int wid   = tid >> 5;

    const float* __restrict__ xb = xyz + (size_t)batch * NPTS * 3;

    __shared__ alignas(16) float s_warp[NWARP][8];      // per-warp winners
    __shared__ alignas(16) float s_slot[2][CSIZE][8];   // cluster candidates

    const int base = rank * PPC + tid;

    // Register-resident point coords and running min distances.
    float px[PPT], py[PPT], pz[PPT], md[PPT];
#pragma unroll
    for (int j = 0; j < PPT; j++) {
        const int p = base + j * TPB;
        px[j] = xb[3 * p + 0];
        py[j] = xb[3 * p + 1];
        pz[j] = xb[3 * p + 2];
        md[j] = 1e10f;            // BIG from the reference
    }

    // First sampled point is index 0 (deterministic variant).
    float cx = xb[0], cy = xb[1], cz = xb[2];
    if (rank == 0 && tid == 0) g_idx[batch * NSAMP] = 0;

    for (int k = 1; k < NSAMP; k++) {
        // --- per-thread: update min_dist, local argmax (value, index, coords) ---
        float bv, bx, by, bz;
        int   bi;
#pragma unroll
        for (int j = 0; j < PPT; j++) {
            const float dx = __fsub_rn(px[j], cx);
            const float dy = __fsub_rn(py[j], cy);
            const float dz = __fsub_rn(pz[j], cz);
            const float d  = __fmaf_rn(dz, dz,
                              __fmaf_rn(dx, dx, __fmul_rn(dy, dy)));
            const float m  = fminf(md[j], d);
            md[j] = m;
            if (j == 0) {
                bv = m; bi = base; bx = px[0]; by = py[0]; bz = pz[0];
            } else if (m > bv) {   // strict >: earlier (lower) index wins ties
                bv = m; bi = base + j * TPB; bx = px[j]; by = py[j]; bz = pz[j];
            }
        }

        // --- warp argmax via REDUX ---
        const uint32_t uv = __float_as_uint(bv);            // bv >= 0
        const uint32_t kv = __reduce_max_sync(0xffffffffu, uv);
        const uint32_t cand = (uv == kv) ? (uint32_t)bi : 0xffffffffu;
        const uint32_t ki = __reduce_min_sync(0xffffffffu, cand);
        if ((uint32_t)bi == ki) {                           // unique winner lane
            *(float4*)&s_warp[wid][0] =
                make_float4(__uint_as_float(kv), __uint_as_float(ki), bx, by);
            s_warp[wid][4] = bz;
        }
        __syncthreads();

        const int b = k & 1;

        // --- warp0: block argmax over 16 warp winners, fan out to all ranks ---
        if (wid == 0) {
            float sv = 0.f, sx = 0.f, sy = 0.f, sz = 0.f;
            uint32_t si = 0xffffffffu;
            if (lane < NWARP) {
                const float4 t = *(const float4*)&s_warp[lane][0];
                sv = t.x; si = __float_as_uint(t.y); sx = t.z; sy = t.w;
                sz = s_warp[lane][4];
            }
            const uint32_t uv2 = __float_as_uint(sv);
            const uint32_t kv2 = __reduce_max_sync(0xffffffffu, uv2);
            const uint32_t c2  = (uv2 == kv2) ? si : 0xffffffffu;
            const uint32_t ki2 = __reduce_min_sync(0xffffffffu, c2);
            const uint32_t m2  = __ballot_sync(0xffffffffu, c2 == ki2); // one-hot
            const int src = __ffs(m2) - 1;
            const float wx = __shfl_sync(0xffffffffu, sx, src);
            const float wy = __shfl_sync(0xffffffffu, sy, src);
            const float wz = __shfl_sync(0xffffffffu, sz, src);
            if (lane < CSIZE) {
                // lane r writes this CTA's candidate into rank r's slot row.
                // Ordering/visibility provided by cluster.sync() below.
                float* dst = (float*)cluster.map_shared_rank(
                    (void*)&s_slot[b][rank][0], lane);
                *(float4*)dst =
                    make_float4(__uint_as_float(kv2), __uint_as_float(ki2), wx, wy);
                dst[4] = wz;
            }
        }

        // release DSMEM stores + cluster barrier + acquire remote stores
        cluster.sync();

        // --- per-warp REDUX combine over the CSIZE slots ---
        float sv = 0.f, sx = 0.f, sy = 0.f, sz = 0.f;
        uint32_t si = 0xffffffffu;
        if (lane < CSIZE) {
            const float4 t = *(const float4*)&s_slot[b][lane][0];
            sv = t.x; si = __float_as_uint(t.y); sx = t.z; sy = t.w;
            sz = s_slot[b][lane][4];
        }
        const uint32_t uv3 = __float_as_uint(sv);
        const uint32_t kv3 = __reduce_max_sync(0xffffffffu, uv3);
        const uint32_t c3  = (uv3 == kv3) ? si : 0xffffffffu;
        const uint32_t ki3 = __reduce_min_sync(0xffffffffu, c3);
        const uint32_t m3  = __ballot_sync(0xffffffffu, c3 == ki3);    // one-hot
        const int src3 = __ffs(m3) - 1;
        cx = __shfl_sync(0xffffffffu, sx, src3);
        cy = __shfl_sync(0xffffffffu, sy, src3);
        cz = __shfl_sync(0xffffffffu, sz, src3);

        if (rank == 0 && tid == 0) g_idx[batch * NSAMP + k] = (int)ki3;
    }
}

// ---------------------------------------------------------------------------
// Gather kernel: one block per sampled row. 256 feature floats (64 x float4)
// plus the 3 xyz floats. Output: [xyz (B,S,3)] then [feature (B,S,256)].
// ---------------------------------------------------------------------------
__global__ void __launch_bounds__(64)
gather_kernel(const float* __restrict__ xyz, const float* __restrict__ feat,
              float* __restrict__ out)
{
    const int row = blockIdx.x;          // 0 .. BATCH*NSAMP-1
    const int b = row / NSAMP;
    const int p = g_idx[row];

    float* out_xyz  = out;
    float* out_feat = out + (size_t)BATCH * NSAMP * 3;

    const float4* src = (const float4*)(feat + ((size_t)b * NPTS + p) * FEATC);
    float4*       dst = (float4*)(out_feat + (size_t)row * FEATC);
    dst[threadIdx.x] = src[threadIdx.x];

    if (threadIdx.x < 3) {
        out_xyz[(size_t)row * 3 + threadIdx.x] =
            xyz[((size_t)b * NPTS + p) * 3 + threadIdx.x];
    }
}

extern "C" void kernel_launch(void* const* d_in, const int* in_sizes, int n_in,
                              void* d_out, int out_size)
{
    const float* xyz  = (const float*)d_in[0];
    const float* feat = (const float*)d_in[1];
    float*       out  = (float*)d_out;

    fps_kernel<<<BATCH * CSIZE, TPB>>>(xyz);
    gather_kernel<<<BATCH * NSAMP, 64>>>(xyz, feat, out);
}